// round 10
// baseline (speedup 1.0000x reference)
#include <cuda_runtime.h>
#include <cuda_fp16.h>
#include <cstdint>
#include <cstring>

// out[n,o,p] = relu( sum_c fea[n,c,p] * W[o,c,0,4] + b[o] )
// GEMM per batch: D[512,4096] = Wc[512,2048] @ fea_n[2048,4096]
// fp16 mma.sync.m16n8k16, fp32 accumulate.
// B (fea) is loaded fp32 via 3-stage cp.async, converted to fp16 by a
// smem->reg->smem hop one iteration ahead of MMA consumption. No separate
// convert pass, no LDG-latency on the critical path.

#define GM 512
#define GN 4096
#define GK 2048
#define NB 8

#define BM 128
#define BN 128
#define BK 32
#define NITER (GK / BK)   // 64
#define NMB (GM / BM)     // 4
#define NPB (GN / BN)     // 32

#define ASTAGES 4
#define B32STAGES 3

// smem layout (bytes)
#define A_ROW_B 80                        // 32 halves + 16B pad
#define A_TILE_B (BM * A_ROW_B)           // 10240
#define B32_ROW_B 528                     // 128 fp32 (512B) + 16B pad
#define B32_TILE_B (BK * B32_ROW_B)       // 16896
#define BH_ROW_B 272                      // 128 halves (256B) + 16B pad
#define BH_TILE_B (BK * BH_ROW_B)         // 8704

#define OFF_A   0
#define OFF_B32 (ASTAGES * A_TILE_B)                  // 40960
#define OFF_BH  (OFF_B32 + B32STAGES * B32_TILE_B)    // 91648
#define SMEM_B  (OFF_BH + 2 * BH_TILE_B)              // 109056

__device__ __align__(16) __half g_Wh[GM * GK];   // 2 MB packed Wc (fp16)

// ---------------------------------------------------------------------------
__device__ __forceinline__ uint32_t smem_u32(const void* p) {
    uint32_t a;
    asm("{ .reg .u64 t; cvta.to.shared.u64 t, %1; cvt.u32.u64 %0, t; }" : "=r"(a) : "l"(p));
    return a;
}
__device__ __forceinline__ void cp16(uint32_t dst, const void* src) {
    asm volatile("cp.async.cg.shared.global [%0], [%1], 16;" :: "r"(dst), "l"(src));
}
#define CP_COMMIT() asm volatile("cp.async.commit_group;" ::: "memory")
template <int N>
__device__ __forceinline__ void cp_wait() {
    asm volatile("cp.async.wait_group %0;" :: "n"(N) : "memory");
}

__device__ __forceinline__ void ldmA(uint32_t* r, uint32_t addr) {
    asm volatile("ldmatrix.sync.aligned.m8n8.x4.shared.b16 {%0,%1,%2,%3}, [%4];"
        : "=r"(r[0]), "=r"(r[1]), "=r"(r[2]), "=r"(r[3]) : "r"(addr));
}
__device__ __forceinline__ void ldmBT(uint32_t* r, uint32_t addr) {
    asm volatile("ldmatrix.sync.aligned.m8n8.x4.trans.shared.b16 {%0,%1,%2,%3}, [%4];"
        : "=r"(r[0]), "=r"(r[1]), "=r"(r[2]), "=r"(r[3]) : "r"(addr));
}
__device__ __forceinline__ void mma16816(float* c, const uint32_t* a, uint32_t b0, uint32_t b1) {
    asm volatile("mma.sync.aligned.m16n8k16.row.col.f32.f16.f16.f32 "
        "{%0,%1,%2,%3}, {%4,%5,%6,%7}, {%8,%9}, {%0,%1,%2,%3};"
        : "+f"(c[0]), "+f"(c[1]), "+f"(c[2]), "+f"(c[3])
        : "r"(a[0]), "r"(a[1]), "r"(a[2]), "r"(a[3]), "r"(b0), "r"(b1));
}
__device__ __forceinline__ uint32_t pkh2(float a, float b) {
    __half2 h = __floats2half2_rn(a, b);
    uint32_t u; memcpy(&u, &h, 4); return u;
}

// ---------------------------------------------------------------------------
// Pack Wc = W[:,:,0,4] -> fp16 row-major [M][K]
__global__ void pack_w_kernel(const float* __restrict__ W) {
    int i = blockIdx.x * blockDim.x + threadIdx.x;
    if (i < GM * GK) g_Wh[i] = __float2half_rn(W[(size_t)i * 9 + 4]);
}

// ---------------------------------------------------------------------------
__global__ __launch_bounds__(256, 2)
void gemm_kernel(const float* __restrict__ fea, const float* __restrict__ bias,
                 float* __restrict__ out) {
    extern __shared__ char smem[];
    const uint32_t sb = smem_u32(smem);

    const int tid  = threadIdx.x;
    const int wid  = tid >> 5;
    const int lane = tid & 31;
    const int mblk = blockIdx.x, pblk = blockIdx.y, nb = blockIdx.z;
    const int wm = wid & 1;        // 2 warps in M (64 rows each)
    const int wn = wid >> 1;       // 4 warps in N (32 cols each)

    const __half* Asrc = g_Wh + (size_t)mblk * BM * GK;                // [m][k] fp16
    const float*  Bsrc = fea + (size_t)nb * GK * GN + pblk * BN;       // [k][n] fp32

    // ---- A cp.async mapping ----
    const int aM  = wid * 8 + (lane & 7);
    const int aKc = (lane >> 3) & 3;

    // ---- B fp32 cp.async mapping: 4 x 16B chunks / thread ----
    const int b32c = tid & 31;                 // 16B-chunk within row (col)
    const int b32r = tid >> 5;                 // base row (0..7), +8 per rep

    // issue chunk kc -> A stage kc%ASTAGES, B32 stage kc%B32STAGES (one commit group)
    auto issue = [&](int kc) {
        const int k0 = kc * BK;
        uint32_t aBase = sb + OFF_A + (kc % ASTAGES) * A_TILE_B;
        cp16(aBase + aM * A_ROW_B + aKc * 16,
             Asrc + (size_t)aM * GK + k0 + aKc * 8);
        cp16(aBase + (aM + 64) * A_ROW_B + aKc * 16,
             Asrc + (size_t)(aM + 64) * GK + k0 + aKc * 8);
        uint32_t bBase = sb + OFF_B32 + (kc % B32STAGES) * B32_TILE_B;
        #pragma unroll
        for (int j = 0; j < 4; ++j) {
            int r = b32r + j * 8;
            cp16(bBase + r * B32_ROW_B + b32c * 16,
                 Bsrc + (size_t)(k0 + r) * GN + b32c * 4);
        }
        CP_COMMIT();
    };

    // convert chunk kc: fp32 stage -> fp16 buf (kc&1). Thread: 16 fp32 of one row.
    const int cvR  = tid >> 3;                 // row 0..31
    const int cvC  = (tid & 7) * 16;           // first fp32 col
    auto convert = [&](int kc) {
        const char* s = smem + OFF_B32 + (kc % B32STAGES) * B32_TILE_B
                      + cvR * B32_ROW_B + cvC * 4;
        char* d = smem + OFF_BH + (kc & 1) * BH_TILE_B + cvR * BH_ROW_B + cvC * 2;
        float4 f0 = *(const float4*)(s);
        float4 f1 = *(const float4*)(s + 16);
        float4 f2 = *(const float4*)(s + 32);
        float4 f3 = *(const float4*)(s + 48);
        *(uint4*)(d)      = make_uint4(pkh2(f0.x, f0.y), pkh2(f0.z, f0.w),
                                       pkh2(f1.x, f1.y), pkh2(f1.z, f1.w));
        *(uint4*)(d + 16) = make_uint4(pkh2(f2.x, f2.y), pkh2(f2.z, f2.w),
                                       pkh2(f3.x, f3.y), pkh2(f3.z, f3.w));
    };

    float acc[4][4][4];
    #pragma unroll
    for (int mt = 0; mt < 4; ++mt)
        #pragma unroll
        for (int nt = 0; nt < 4; ++nt)
            #pragma unroll
            for (int j = 0; j < 4; ++j) acc[mt][nt][j] = 0.0f;

    // ---- prologue: chunks 0,1,2 in flight; convert chunk 0 ----
    issue(0); issue(1); issue(2);
    cp_wait<2>();
    __syncthreads();
    convert(0);

    const uint32_t aLdOff = (uint32_t)(wm * 64 + (lane & 15)) * A_ROW_B + ((lane >> 4) * 8) * 2;
    const uint32_t bLdOff = (uint32_t)(lane & 15) * BH_ROW_B + (wn * 32 + (lane >> 4) * 8) * 2;

    for (int i = 0; i < NITER; ++i) {
        // chunks <= i+1 complete (fp32 i+1 ready to convert; A chunk i ready)
        cp_wait<1>();
        __syncthreads();   // orders: convert(i) STS visible; frees stage i%B32STAGES reads

        if (i + 3 < NITER) issue(i + 3);
        else               CP_COMMIT();        // keep group count uniform
        if (i + 1 < NITER) convert(i + 1);

        const uint32_t aBase = sb + OFF_A + (i % ASTAGES) * A_TILE_B;
        const uint32_t bBase = sb + OFF_BH + (i & 1) * BH_TILE_B;

        #pragma unroll
        for (int ks = 0; ks < 2; ++ks) {
            const int k0 = ks * 16;
            uint32_t afr[4][4];
            #pragma unroll
            for (int mt = 0; mt < 4; ++mt)
                ldmA(afr[mt], aBase + aLdOff + (uint32_t)mt * 16 * A_ROW_B + k0 * 2);
            uint32_t bfr[2][4];
            uint32_t bAddr = bBase + bLdOff + (uint32_t)k0 * BH_ROW_B;
            ldmBT(bfr[0], bAddr);        // n-tiles 0,1
            ldmBT(bfr[1], bAddr + 32);   // n-tiles 2,3
            #pragma unroll
            for (int mt = 0; mt < 4; ++mt)
                #pragma unroll
                for (int nt = 0; nt < 4; ++nt)
                    mma16816(acc[mt][nt], afr[mt],
                             bfr[nt >> 1][(nt & 1) * 2], bfr[nt >> 1][(nt & 1) * 2 + 1]);
        }
    }

    // ---- epilogue: bias + relu ----
    const int row0 = mblk * BM + wm * 64 + (lane >> 2);
    const int col0 = pblk * BN + wn * 32 + (lane & 3) * 2;
    #pragma unroll
    for (int mt = 0; mt < 4; ++mt) {
        const int r = row0 + mt * 16;
        const float bv0 = bias[r];
        const float bv1 = bias[r + 8];
        float* p0 = out + ((size_t)nb * GM + r) * GN + col0;
        float* p1 = p0 + (size_t)8 * GN;
        #pragma unroll
        for (int nt = 0; nt < 4; ++nt) {
            float2 v0, v1;
            v0.x = fmaxf(acc[mt][nt][0] + bv0, 0.0f);
            v0.y = fmaxf(acc[mt][nt][1] + bv0, 0.0f);
            v1.x = fmaxf(acc[mt][nt][2] + bv1, 0.0f);
            v1.y = fmaxf(acc[mt][nt][3] + bv1, 0.0f);
            *(float2*)(p0 + nt * 8) = v0;
            *(float2*)(p1 + nt * 8) = v1;
        }
    }
}

// ---------------------------------------------------------------------------
extern "C" void kernel_launch(void* const* d_in, const int* in_sizes, int n_in,
                              void* d_out, int out_size) {
    const float* fea  = (const float*)d_in[0];
    const float* W    = (const float*)d_in[1];
    const float* bias = (const float*)d_in[2];
    float* out = (float*)d_out;

    static bool attr_set = false;
    if (!attr_set) {
        cudaFuncSetAttribute(gemm_kernel, cudaFuncAttributeMaxDynamicSharedMemorySize, SMEM_B);
        attr_set = true;
    }

    pack_w_kernel<<<(GM * GK + 255) / 256, 256>>>(W);
    gemm_kernel<<<dim3(NMB, NPB, NB), 256, SMEM_B>>>(fea, bias, out);
}

// round 11
// speedup vs baseline: 1.1370x; 1.1370x over previous
#include <cuda_runtime.h>
#include <cuda_fp16.h>
#include <cstdint>
#include <cstring>

// out[n,o,p] = relu( sum_c fea[n,c,p] * W[o,c,0,4] + b[o] )
// GEMM per batch: D[512,4096] = Wc[512,2048] @ fea_n[2048,4096]
// Two-pass: (1) convert fea fp32->fp16 (streaming), (2) fp16 HMMA GEMM.
// GEMM: BK=64 K-chunks (32 iterations), 3-stage cp.async, 128x128 CTA tile.

#define GM 512
#define GN 4096
#define GK 2048
#define NB 8

#define BM 128
#define BN 128
#define BK 64
#define STAGES 3
#define NITER (GK / BK)   // 32
#define NMB (GM / BM)     // 4
#define NPB (GN / BN)     // 32

// smem layout (bytes): padded rows for conflict-free ldmatrix
#define A_ROW_B 144                     // 64 halves (128B) + 16B pad
#define A_TILE_B (BM * A_ROW_B)         // 18432
#define B_ROW_B 272                     // 128 halves (256B) + 16B pad
#define B_TILE_B (BK * B_ROW_B)         // 17408
#define STAGE_B (A_TILE_B + B_TILE_B)   // 35840
#define SMEM_B (STAGES * STAGE_B)       // 107520

__device__ __align__(16) __half g_Wh[GM * GK];                 // 2 MB
__device__ __align__(16) __half g_feaH[(size_t)NB * GK * GN];  // 134 MB

// ---------------------------------------------------------------------------
__device__ __forceinline__ uint32_t smem_u32(const void* p) {
    uint32_t a;
    asm("{ .reg .u64 t; cvta.to.shared.u64 t, %1; cvt.u32.u64 %0, t; }" : "=r"(a) : "l"(p));
    return a;
}
__device__ __forceinline__ void cp16(uint32_t dst, const void* src) {
    asm volatile("cp.async.cg.shared.global [%0], [%1], 16;" :: "r"(dst), "l"(src));
}
#define CP_COMMIT() asm volatile("cp.async.commit_group;" ::: "memory")
template <int N>
__device__ __forceinline__ void cp_wait() {
    asm volatile("cp.async.wait_group %0;" :: "n"(N) : "memory");
}

__device__ __forceinline__ void ldmA(uint32_t* r, uint32_t addr) {
    asm volatile("ldmatrix.sync.aligned.m8n8.x4.shared.b16 {%0,%1,%2,%3}, [%4];"
        : "=r"(r[0]), "=r"(r[1]), "=r"(r[2]), "=r"(r[3]) : "r"(addr));
}
__device__ __forceinline__ void ldmBT(uint32_t* r, uint32_t addr) {
    asm volatile("ldmatrix.sync.aligned.m8n8.x4.trans.shared.b16 {%0,%1,%2,%3}, [%4];"
        : "=r"(r[0]), "=r"(r[1]), "=r"(r[2]), "=r"(r[3]) : "r"(addr));
}
__device__ __forceinline__ void mma16816(float* c, const uint32_t* a, uint32_t b0, uint32_t b1) {
    asm volatile("mma.sync.aligned.m16n8k16.row.col.f32.f16.f16.f32 "
        "{%0,%1,%2,%3}, {%4,%5,%6,%7}, {%8,%9}, {%0,%1,%2,%3};"
        : "+f"(c[0]), "+f"(c[1]), "+f"(c[2]), "+f"(c[3])
        : "r"(a[0]), "r"(a[1]), "r"(a[2]), "r"(a[3]), "r"(b0), "r"(b1));
}

// ---------------------------------------------------------------------------
// Pack Wc = W[:,:,0,4] -> fp16 row-major [M][K]
__global__ void pack_w_kernel(const float* __restrict__ W) {
    int i = blockIdx.x * blockDim.x + threadIdx.x;
    if (i < GM * GK) g_Wh[i] = __float2half_rn(W[(size_t)i * 9 + 4]);
}

// Convert fea fp32 -> fp16 (pure streaming)
__global__ __launch_bounds__(256)
void convert_fea_kernel(const float* __restrict__ fea) {
    size_t i = ((size_t)blockIdx.x * 256 + threadIdx.x) * 8;
    float4 f0 = *(const float4*)(fea + i);
    float4 f1 = *(const float4*)(fea + i + 4);
    __half2 h[4];
    h[0] = __floats2half2_rn(f0.x, f0.y);
    h[1] = __floats2half2_rn(f0.z, f0.w);
    h[2] = __floats2half2_rn(f1.x, f1.y);
    h[3] = __floats2half2_rn(f1.z, f1.w);
    uint4 v;
    memcpy(&v, h, 16);
    *(uint4*)(g_feaH + i) = v;
}

// ---------------------------------------------------------------------------
__global__ __launch_bounds__(256, 2)
void gemm_kernel(const float* __restrict__ bias, float* __restrict__ out) {
    extern __shared__ char smem[];
    const uint32_t sb = smem_u32(smem);

    const int tid  = threadIdx.x;
    const int wid  = tid >> 5;
    const int lane = tid & 31;
    const int mblk = blockIdx.x, pblk = blockIdx.y, nb = blockIdx.z;
    const int wm = wid & 1;        // 2 warps in M (64 rows each)
    const int wn = wid >> 1;       // 4 warps in N (32 cols each)

    const __half* Asrc = g_Wh + (size_t)mblk * BM * GK;                 // [m][k]
    const __half* Bsrc = g_feaH + (size_t)nb * GK * GN + pblk * BN;     // [k][n]

    // ---- cp.async mappings: 4 chunks A + 4 chunks B per thread per stage ----
    const int aRow  = tid >> 1;                // 0..127
    const int aCol  = (tid & 1) * 64;          // byte offset within 128B row
    const int bRow  = tid >> 2;                // 0..63
    const int bCol  = (tid & 3) * 64;          // byte offset within 256B row

    auto issue_stage = [&](int s, int kchunk) {
        const int k0 = kchunk * BK;
        uint32_t aBase = sb + s * STAGE_B;
        uint32_t bBase = aBase + A_TILE_B;
        const __half* ag = Asrc + (size_t)aRow * GK + k0 + (aCol >> 1);
        uint32_t ad = aBase + aRow * A_ROW_B + aCol;
        #pragma unroll
        for (int j = 0; j < 4; ++j) cp16(ad + j * 16, ag + j * 8);
        const __half* bg = Bsrc + (size_t)(k0 + bRow) * GN + (bCol >> 1);
        uint32_t bd = bBase + bRow * B_ROW_B + bCol;
        #pragma unroll
        for (int j = 0; j < 4; ++j) cp16(bd + j * 16, bg + j * 8);
        CP_COMMIT();
    };

    float acc[4][4][4];
    #pragma unroll
    for (int mt = 0; mt < 4; ++mt)
        #pragma unroll
        for (int nt = 0; nt < 4; ++nt)
            #pragma unroll
            for (int j = 0; j < 4; ++j) acc[mt][nt][j] = 0.0f;

    issue_stage(0, 0);
    issue_stage(1, 1);

    const uint32_t aLdOff = (uint32_t)(wm * 64 + (lane & 15)) * A_ROW_B + ((lane >> 4) * 8) * 2;
    const uint32_t bLdOff = (uint32_t)(lane & 15) * B_ROW_B + (wn * 32 + (lane >> 4) * 8) * 2;

    for (int i = 0; i < NITER; ++i) {
        const int s = i % STAGES;
        if (i < NITER - 1) cp_wait<1>(); else cp_wait<0>();
        __syncthreads();

        if (i + 2 < NITER) issue_stage((i + 2) % STAGES, i + 2);

        const uint32_t aBase = sb + s * STAGE_B;
        const uint32_t bBase = aBase + A_TILE_B;

        #pragma unroll
        for (int ks = 0; ks < 4; ++ks) {
            const int k0 = ks * 16;
            uint32_t afr[4][4];
            #pragma unroll
            for (int mt = 0; mt < 4; ++mt)
                ldmA(afr[mt], aBase + aLdOff + (uint32_t)mt * 16 * A_ROW_B + k0 * 2);
            uint32_t bfr[2][4];
            uint32_t bAddr = bBase + bLdOff + (uint32_t)k0 * B_ROW_B;
            ldmBT(bfr[0], bAddr);        // n-tiles 0,1
            ldmBT(bfr[1], bAddr + 32);   // n-tiles 2,3
            #pragma unroll
            for (int mt = 0; mt < 4; ++mt)
                #pragma unroll
                for (int nt = 0; nt < 4; ++nt)
                    mma16816(acc[mt][nt], afr[mt],
                             bfr[nt >> 1][(nt & 1) * 2], bfr[nt >> 1][(nt & 1) * 2 + 1]);
        }
    }

    // ---- epilogue: bias + relu ----
    const int row0 = mblk * BM + wm * 64 + (lane >> 2);
    const int col0 = pblk * BN + wn * 32 + (lane & 3) * 2;
    #pragma unroll
    for (int mt = 0; mt < 4; ++mt) {
        const int r = row0 + mt * 16;
        const float bv0 = bias[r];
        const float bv1 = bias[r + 8];
        float* p0 = out + ((size_t)nb * GM + r) * GN + col0;
        float* p1 = p0 + (size_t)8 * GN;
        #pragma unroll
        for (int nt = 0; nt < 4; ++nt) {
            float2 v0, v1;
            v0.x = fmaxf(acc[mt][nt][0] + bv0, 0.0f);
            v0.y = fmaxf(acc[mt][nt][1] + bv0, 0.0f);
            v1.x = fmaxf(acc[mt][nt][2] + bv1, 0.0f);
            v1.y = fmaxf(acc[mt][nt][3] + bv1, 0.0f);
            *(float2*)(p0 + nt * 8) = v0;
            *(float2*)(p1 + nt * 8) = v1;
        }
    }
}

// ---------------------------------------------------------------------------
extern "C" void kernel_launch(void* const* d_in, const int* in_sizes, int n_in,
                              void* d_out, int out_size) {
    const float* fea  = (const float*)d_in[0];
    const float* W    = (const float*)d_in[1];
    const float* bias = (const float*)d_in[2];
    float* out = (float*)d_out;

    static bool attr_set = false;
    if (!attr_set) {
        cudaFuncSetAttribute(gemm_kernel, cudaFuncAttributeMaxDynamicSharedMemorySize, SMEM_B);
        attr_set = true;
    }

    pack_w_kernel<<<(GM * GK + 255) / 256, 256>>>(W);
    {
        size_t total = (size_t)NB * GK * GN;            // 67108864
        int blocks = (int)(total / (256 * 8));          // 32768
        convert_fea_kernel<<<blocks, 256>>>(fea);
    }
    gemm_kernel<<<dim3(NMB, NPB, NB), 256, SMEM_B>>>(bias, out);
}